// round 12
// baseline (speedup 1.0000x reference)
#include <cuda_runtime.h>
#include <cuda_fp16.h>
#include <cstdint>
#include <cstddef>

// ---------------------------------------------------------------------------
// WindowAttention (Swin) on GB300 — Round 12.
// GEMMs: R8 config verbatim. Attention: tensor-core QK^T and AV per (w,h),
// scalar softmax in smem (max-free, fixed shift), deferred normalization.
// Launch order puts attn 4th so ncu captures it.
// ---------------------------------------------------------------------------

#define NWIN      8192
#define NTOK      49
#define DIM       384
#define NHEAD     12
#define HEADD     32
#define NW_IMG    64
#define MROWS     (NWIN * NTOK)        // 401408
#define QKV_COLS  1152
#define K2        768                  // split K: hi | lo
#define SCALE_F   0.17677669529663687f
#define EXP_SHIFT 5.545177444479562f   // 8*ln2 headroom for fp16 P

// Device scratch
__device__ float  g_qkv[(size_t)MROWS * QKV_COLS];
__device__ __half g_x2[(size_t)MROWS * K2];
__device__ __half g_attn2[(size_t)MROWS * K2];
__device__ __half g_wqkv2[(size_t)QKV_COLS * K2];
__device__ __half g_wproj2[(size_t)DIM * K2];
__device__ float  g_bias[NHEAD * NTOK * NTOK];   // [h][i][j]

// ---------------------------------------------------------------------------
// Helpers
// ---------------------------------------------------------------------------
__device__ __forceinline__ uint32_t smem_u32(const void* p) {
    uint32_t a;
    asm("{ .reg .u64 t; cvta.to.shared.u64 t, %1; cvt.u32.u64 %0, t; }"
        : "=r"(a) : "l"(p));
    return a;
}

__device__ __forceinline__ void cpa16(uint32_t dst, const void* src) {
    asm volatile("cp.async.cg.shared.global [%0], [%1], 16;"
                 :: "r"(dst), "l"(src));
}

__device__ __forceinline__ void ldsm_x4(uint32_t* r, uint32_t addr) {
    asm volatile("ldmatrix.sync.aligned.m8n8.x4.shared.b16 {%0,%1,%2,%3}, [%4];"
                 : "=r"(r[0]), "=r"(r[1]), "=r"(r[2]), "=r"(r[3])
                 : "r"(addr));
}

__device__ __forceinline__ void mma16816(float* d, const uint32_t* a,
                                         const uint32_t* b) {
    asm volatile(
        "mma.sync.aligned.m16n8k16.row.col.f32.f16.f16.f32 "
        "{%0,%1,%2,%3}, {%4,%5,%6,%7}, {%8,%9}, {%0,%1,%2,%3};"
        : "+f"(d[0]), "+f"(d[1]), "+f"(d[2]), "+f"(d[3])
        : "r"(a[0]), "r"(a[1]), "r"(a[2]), "r"(a[3]),
          "r"(b[0]), "r"(b[1]));
}

// exp(x) on the FMA pipe: 2^(x*log2e), deg-5 poly, rel err ~2.4e-6.
__device__ __forceinline__ float fast_exp(float x) {
    float t = fmaxf(x, -80.0f) * 1.442695040888963f;
    float r = rintf(t);
    float f = t - r;
    float p =             1.3333558e-3f;
    p = fmaf(p, f, 9.6181291e-3f);
    p = fmaf(p, f, 5.5504109e-2f);
    p = fmaf(p, f, 2.4022651e-1f);
    p = fmaf(p, f, 6.9314718e-1f);
    p = fmaf(p, f, 1.0f);
    int ri = (int)r;
    return __int_as_float(__float_as_int(p) + ri * 8388608);
}

// ---------------------------------------------------------------------------
// Merged prep kernel: splits x (act hi|lo), qkv_w and proj_w (wgt hi|hi).
// ---------------------------------------------------------------------------
__global__ void prep_all(const float* __restrict__ x,
                         const float* __restrict__ qkv_w,
                         const float* __restrict__ proj_w,
                         __half* __restrict__ x2,
                         __half* __restrict__ wq2,
                         __half* __restrict__ wp2,
                         long t4x, long t4wq, long t4wp)
{
    long idx = (long)blockIdx.x * blockDim.x + threadIdx.x;
    const float* in;
    __half* out;
    bool act;
    if (idx < t4x)                    { in = x;      out = x2;  act = true; }
    else if (idx < t4x + t4wq)        { idx -= t4x;  in = qkv_w; out = wq2; act = false; }
    else if (idx < t4x + t4wq + t4wp) { idx -= t4x + t4wq; in = proj_w; out = wp2; act = false; }
    else return;

    long r = idx / (DIM / 4);
    int  c4 = (int)(idx - r * (DIM / 4));
    float4 v = *((const float4*)(in + r * DIM) + c4);
    float a[4] = {v.x, v.y, v.z, v.w};
    __half hi[4], lo[4];
    #pragma unroll
    for (int i = 0; i < 4; i++) {
        hi[i] = __float2half_rn(a[i]);
        lo[i] = __float2half_rn(a[i] - __half2float(hi[i]));
    }
    __half2 h0 = __halves2half2(hi[0], hi[1]);
    __half2 h1 = __halves2half2(hi[2], hi[3]);
    __half2* s0 = (__half2*)(out + r * K2 + c4 * 4);
    __half2* s1 = (__half2*)(out + r * K2 + DIM + c4 * 4);
    s0[0] = h0; s0[1] = h1;
    if (act) {
        s1[0] = __halves2half2(lo[0], lo[1]);
        s1[1] = __halves2half2(lo[2], lo[3]);
    } else {
        s1[0] = h0; s1[1] = h1;
    }
}

__global__ void bias_prep_kernel(const float* __restrict__ rel_table,
                                 const int* __restrict__ rel_idx)
{
    int t = blockIdx.x * blockDim.x + threadIdx.x;
    if (t >= NHEAD * NTOK * NTOK) return;
    int h   = t / (NTOK * NTOK);
    int idx = t - h * (NTOK * NTOK);
    g_bias[t] = rel_table[rel_idx[idx] * NHEAD + h];
}

// ---------------------------------------------------------------------------
// HMMA GEMM (R8 config, verbatim)
// ---------------------------------------------------------------------------
#define BKC       64
#define NCH       (K2 / BKC)
#define TILE_BYTES 16384
#define STAGE_BYTES (2 * TILE_BYTES)
#define GSMEM     (2 * STAGE_BYTES + 128)

__global__ __launch_bounds__(256, 2)
void gemm_mma(const __half* __restrict__ A,
              const __half* __restrict__ B,
              const float* __restrict__ bias,
              float* __restrict__ C, int Nn)
{
    extern __shared__ uint8_t smem_raw[];
    const int tid  = threadIdx.x;
    const int warp = tid >> 5;
    const int lane = tid & 31;

    uint32_t sraw  = smem_u32(smem_raw);
    uint32_t sbase = (sraw + 127u) & ~127u;

    const int m0 = blockIdx.y << 7;
    const int n0 = blockIdx.x << 7;

    const char* Ag = (const char*)(A + (size_t)m0 * K2);
    const char* Bg = (const char*)(B + (size_t)n0 * K2);
    uint32_t sw[4];
    size_t   go[4];
    #pragma unroll
    for (int i = 0; i < 4; i++) {
        int u = i * 256 + tid;
        int r = u >> 3, c = u & 7;
        sw[i] = (uint32_t)(r * 128 + ((c ^ (r & 7)) << 4));
        go[i] = (size_t)r * (K2 * 2) + (size_t)c * 16;
    }

    auto load_chunk = [&](int c, int s) {
        uint32_t ab = sbase + s * STAGE_BYTES;
        uint32_t bb = ab + TILE_BYTES;
        size_t koff = (size_t)c * 128;
        #pragma unroll
        for (int i = 0; i < 4; i++) {
            cpa16(ab + sw[i], Ag + go[i] + koff);
            cpa16(bb + sw[i], Bg + go[i] + koff);
        }
        asm volatile("cp.async.commit_group;" ::: "memory");
    };

    const int wm = warp & 1;
    const int wn = warp >> 1;
    const int l15 = lane & 15;
    const int lhi = lane >> 4;
    const int g8  = lane >> 3;
    const int l8  = lane & 7;

    int rA[4], rowOffA[4];
    #pragma unroll
    for (int mf = 0; mf < 4; mf++) {
        rA[mf] = wm * 64 + mf * 16 + l15;
        rowOffA[mf] = rA[mf] * 128;
    }
    int rB[2], rowOffB[2];
    #pragma unroll
    for (int p = 0; p < 2; p++) {
        rB[p] = wn * 32 + p * 16 + (g8 >> 1) * 8 + l8;
        rowOffB[p] = rB[p] * 128;
    }

    float acc[4][4][4];
    #pragma unroll
    for (int mf = 0; mf < 4; mf++)
        #pragma unroll
        for (int nf = 0; nf < 4; nf++)
            #pragma unroll
            for (int e = 0; e < 4; e++) acc[mf][nf][e] = 0.0f;

    load_chunk(0, 0);

    for (int c = 0; c < NCH; ++c) {
        if (c + 1 < NCH) {
            load_chunk(c + 1, (c + 1) & 1);
            asm volatile("cp.async.wait_group 1;" ::: "memory");
        } else {
            asm volatile("cp.async.wait_group 0;" ::: "memory");
        }
        __syncthreads();

        const uint32_t aT = sbase + (c & 1) * STAGE_BYTES;
        const uint32_t bT = aT + TILE_BYTES;

        #pragma unroll
        for (int ks = 0; ks < 4; ++ks) {
            uint32_t af[4][4];
            #pragma unroll
            for (int mf = 0; mf < 4; mf++) {
                const int c16 = ks * 2 + lhi;
                ldsm_x4(af[mf], aT + rowOffA[mf] +
                                ((c16 ^ (rA[mf] & 7)) << 4));
            }
            uint32_t bf[2][4];
            #pragma unroll
            for (int p = 0; p < 2; p++) {
                const int c16 = ks * 2 + (g8 & 1);
                ldsm_x4(bf[p], bT + rowOffB[p] +
                               ((c16 ^ (rB[p] & 7)) << 4));
            }
            #pragma unroll
            for (int mf = 0; mf < 4; mf++) {
                mma16816(acc[mf][0], af[mf], &bf[0][0]);
                mma16816(acc[mf][1], af[mf], &bf[0][2]);
                mma16816(acc[mf][2], af[mf], &bf[1][0]);
                mma16816(acc[mf][3], af[mf], &bf[1][2]);
            }
        }
        __syncthreads();
    }

    const int colBase = n0 + wn * 32 + 2 * (lane & 3);
    float2 b2[4];
    #pragma unroll
    for (int nf = 0; nf < 4; nf++)
        b2[nf] = *(const float2*)(bias + colBase + nf * 8);

    const int rowBase = m0 + wm * 64 + (lane >> 2);
    #pragma unroll
    for (int mf = 0; mf < 4; mf++) {
        const int r0 = rowBase + mf * 16;
        #pragma unroll
        for (int nf = 0; nf < 4; nf++) {
            const int col = colBase + nf * 8;
            float2 v0 = make_float2(acc[mf][nf][0] + b2[nf].x,
                                    acc[mf][nf][1] + b2[nf].y);
            float2 v1 = make_float2(acc[mf][nf][2] + b2[nf].x,
                                    acc[mf][nf][3] + b2[nf].y);
            *(float2*)(C + (size_t)r0 * Nn + col)       = v0;
            *(float2*)(C + (size_t)(r0 + 8) * Nn + col) = v1;
        }
    }
}

// ---------------------------------------------------------------------------
// Tensor-core attention: grid (NWIN, NHEAD), 128 threads (4 warps).
// smem layout (bytes from 128B-aligned base):
//   QA1 [hiQ|hiQ] 0..8191, QA2 [loQ|loQ] 8192..16383, KB [hiK|loK] 16384..24575
//   S fp32 64x66  0..16895 (overlays QA/KB after QK mma)
//   PH 24576 (8KB), PL 32768 (8KB), VT 40960 (4KB), BM 45056 (9616), RS 54672
// ---------------------------------------------------------------------------
#define A_QA1 0
#define A_QA2 8192
#define A_KB  16384
#define A_S   0
#define A_PH  24576
#define A_PL  32768
#define A_VT  40960
#define A_BM  45056
#define A_RS  54672
#define ASMEM (54672 + 256 + 128)

__device__ __forceinline__ uint32_t tile_addr(uint32_t tile, int row, int j) {
    // 128B rows, XOR-8 swizzle on 16B chunks; j = fp16 column
    return tile + row * 128 + ((((j >> 3) ^ (row & 7)) << 4) | ((j & 7) * 2));
}

__global__ __launch_bounds__(128)
void attn_tc_kernel(const float* __restrict__ mask)
{
    extern __shared__ uint8_t asm_raw[];
    const int tid  = threadIdx.x;
    const int warp = tid >> 5;
    const int lane = tid & 31;
    const int w    = blockIdx.x;
    const int h    = blockIdx.y;

    uint32_t sraw  = smem_u32(asm_raw);
    uint32_t sb    = (sraw + 127u) & ~127u;
    uint8_t* smem  = asm_raw + (sb - sraw);

    // ---- zero QA1/QA2/KB (24KB) and VT (4KB) ----
    {
        uint4 z = make_uint4(0, 0, 0, 0);
        uint4* p0 = (uint4*)(smem + A_QA1);
        for (int u = tid; u < 24576 / 16; u += 128) p0[u] = z;
        uint4* p1 = (uint4*)(smem + A_VT);
        for (int u = tid; u < 4096 / 16; u += 128) p1[u] = z;
    }
    __syncthreads();

    // ---- load qkv, build fp16 tiles ----
    const size_t base0 = (size_t)w * NTOK * QKV_COLS + h * HEADD;
    for (int idx = tid; idx < NTOK * 8; idx += 128) {
        const int i = idx >> 3, c4 = idx & 7, d0 = c4 * 4;
        const float* gp = g_qkv + base0 + (size_t)i * QKV_COLS + d0;
        float4 qv = *(const float4*)gp;
        float4 kv = *(const float4*)(gp + 384);
        float4 vv = *(const float4*)(gp + 768);
        float qa[4] = {qv.x * SCALE_F, qv.y * SCALE_F,
                       qv.z * SCALE_F, qv.w * SCALE_F};
        float ka[4] = {kv.x, kv.y, kv.z, kv.w};
        float va[4] = {vv.x, vv.y, vv.z, vv.w};
        __half qh[4], ql[4], kh[4], kl[4];
        #pragma unroll
        for (int m = 0; m < 4; m++) {
            qh[m] = __float2half_rn(qa[m]);
            ql[m] = __float2half_rn(qa[m] - __half2float(qh[m]));
            kh[m] = __float2half_rn(ka[m]);
            kl[m] = __float2half_rn(ka[m] - __half2float(kh[m]));
        }
        uint32_t qhp[2] = {((uint32_t*)qh)[0], ((uint32_t*)qh)[1]};
        uint32_t qlp[2] = {((uint32_t*)ql)[0], ((uint32_t*)ql)[1]};
        uint32_t khp[2] = {((uint32_t*)kh)[0], ((uint32_t*)kh)[1]};
        uint32_t klp[2] = {((uint32_t*)kl)[0], ((uint32_t*)kl)[1]};
        // QA1 = [hiQ|hiQ], QA2 = [loQ|loQ], KB = [hiK|loK]
        *(uint2*)(smem + (tile_addr(A_QA1, i, d0)      - 0)) = make_uint2(qhp[0], qhp[1]);
        *(uint2*)(smem + (tile_addr(A_QA1, i, d0 + 32) - 0)) = make_uint2(qhp[0], qhp[1]);
        *(uint2*)(smem + (tile_addr(A_QA2, i, d0)      - 0)) = make_uint2(qlp[0], qlp[1]);
        *(uint2*)(smem + (tile_addr(A_QA2, i, d0 + 32) - 0)) = make_uint2(qlp[0], qlp[1]);
        *(uint2*)(smem + (tile_addr(A_KB,  i, d0)      - 0)) = make_uint2(khp[0], khp[1]);
        *(uint2*)(smem + (tile_addr(A_KB,  i, d0 + 32) - 0)) = make_uint2(klp[0], klp[1]);
        // VT[d][i] = hi(v[i][d]) (transposed)
        #pragma unroll
        for (int m = 0; m < 4; m++) {
            __half vh = __float2half_rn(va[m]);
            *(__half*)(smem + tile_addr(A_VT, d0 + m, i)) = vh;
        }
    }
    // BM = bias + mask (fp32, [i][j] packed stride 49)
    {
        const float* mrow = mask + (size_t)(w & (NW_IMG - 1)) * (NTOK * NTOK);
        const float* brow = g_bias + h * (NTOK * NTOK);
        float* BM = (float*)(smem + A_BM);
        for (int idx = tid; idx < NTOK * NTOK; idx += 128)
            BM[idx] = brow[idx] + mrow[idx];
    }
    __syncthreads();

    const int l15 = lane & 15;
    const int lhi = lane >> 4;
    const int g8  = lane >> 3;
    const int l8  = lane & 7;

    // ---- QK^T: two passes (QA1, QA2) vs KB -> S ----
    float sacc[8][4];
    #pragma unroll
    for (int nf = 0; nf < 8; nf++)
        #pragma unroll
        for (int e = 0; e < 4; e++) sacc[nf][e] = 0.0f;
    {
        const int rA = warp * 16 + l15;
        int rB[4];
        #pragma unroll
        for (int p = 0; p < 4; p++) rB[p] = p * 16 + (g8 >> 1) * 8 + l8;

        #pragma unroll
        for (int pass = 0; pass < 2; pass++) {
            const uint32_t aTile = pass ? A_QA2 : A_QA1;
            #pragma unroll
            for (int ks = 0; ks < 4; ks++) {
                uint32_t af[4];
                const int c16a = ks * 2 + lhi;
                ldsm_x4(af, sb + aTile + rA * 128 + ((c16a ^ (rA & 7)) << 4));
                uint32_t bf[4][4];
                #pragma unroll
                for (int p = 0; p < 4; p++) {
                    const int c16b = ks * 2 + (g8 & 1);
                    ldsm_x4(bf[p], sb + A_KB + rB[p] * 128 +
                                   ((c16b ^ (rB[p] & 7)) << 4));
                }
                #pragma unroll
                for (int p = 0; p < 4; p++) {
                    mma16816(sacc[2 * p],     af, &bf[p][0]);
                    mma16816(sacc[2 * p + 1], af, &bf[p][2]);
                }
            }
        }
    }
    __syncthreads();   // all warps done reading QA/KB before S overlays them

    // ---- store S (fp32, stride 66) ----
    {
        float* S = (float*)(smem + A_S);
        const int r0 = warp * 16 + (lane >> 2);
        const int cb = 2 * (lane & 3);
        #pragma unroll
        for (int nf = 0; nf < 8; nf++) {
            const int col = nf * 8 + cb;
            *(float2*)&S[r0 * 66 + col]       = make_float2(sacc[nf][0], sacc[nf][1]);
            *(float2*)&S[(r0 + 8) * 66 + col] = make_float2(sacc[nf][2], sacc[nf][3]);
        }
    }
    __syncthreads();

    // ---- exp + P (fp16 hi|lo tiles) ----
    {
        float* S = (float*)(smem + A_S);
        const float* BM = (const float*)(smem + A_BM);
        for (int idx = tid; idx < NTOK * 64; idx += 128) {
            const int i = idx >> 6, j = idx & 63;
            float e = 0.0f;
            if (j < NTOK) {
                e = fast_exp(S[i * 66 + j] + BM[i * NTOK + j] - EXP_SHIFT);
                S[i * 66 + j] = e;
            }
            const __half hi = __float2half_rn(e);
            const __half lo = __float2half_rn(e - __half2float(hi));
            *(__half*)(smem + tile_addr(A_PH, i, j)) = hi;
            *(__half*)(smem + tile_addr(A_PL, i, j)) = lo;
        }
    }
    __syncthreads();

    // ---- row sums -> reciprocals ----
    if (tid < NTOK) {
        const float* Sr = (const float*)(smem + A_S) + tid * 66;
        float s0 = 0.0f, s1 = 0.0f, s2 = 0.0f, s3 = 0.0f;
        int j = 0;
        for (; j + 4 <= NTOK; j += 4) {
            s0 += Sr[j]; s1 += Sr[j + 1]; s2 += Sr[j + 2]; s3 += Sr[j + 3];
        }
        for (; j < NTOK; ++j) s0 += Sr[j];
        ((float*)(smem + A_RS))[tid] = 1.0f / ((s0 + s1) + (s2 + s3));
    }
    __syncthreads();

    // ---- AV: (PH then PL) @ VT -> O ----
    float oacc[4][4];
    #pragma unroll
    for (int nf = 0; nf < 4; nf++)
        #pragma unroll
        for (int e = 0; e < 4; e++) oacc[nf][e] = 0.0f;
    {
        const int rA = warp * 16 + l15;
        int rB[2];
        #pragma unroll
        for (int p = 0; p < 2; p++) rB[p] = p * 16 + (g8 >> 1) * 8 + l8;

        #pragma unroll
        for (int pass = 0; pass < 2; pass++) {
            const uint32_t aTile = pass ? A_PL : A_PH;
            #pragma unroll
            for (int ks = 0; ks < 4; ks++) {
                uint32_t af[4];
                const int c16a = ks * 2 + lhi;
                ldsm_x4(af, sb + aTile + rA * 128 + ((c16a ^ (rA & 7)) << 4));
                uint32_t bf[2][4];
                #pragma unroll
                for (int p = 0; p < 2; p++) {
                    const int c16b = ks * 2 + (g8 & 1);
                    ldsm_x4(bf[p], sb + A_VT + rB[p] * 128 +
                                   ((c16b ^ (rB[p] & 7)) << 4));
                }
                mma16816(oacc[0], af, &bf[0][0]);
                mma16816(oacc[1], af, &bf[0][2]);
                mma16816(oacc[2], af, &bf[1][0]);
                mma16816(oacc[3], af, &bf[1][2]);
            }
        }
    }

    // ---- epilogue: scale by 1/rowsum, split fp16, store ----
    {
        const float* RS = (const float*)(smem + A_RS);
        const int r0 = warp * 16 + (lane >> 2);
        const int cb = 2 * (lane & 3);
        #pragma unroll
        for (int hf = 0; hf < 2; hf++) {
            const int row = r0 + hf * 8;
            if (row < NTOK) {
                const float rs = RS[row];
                __half* gp = g_attn2 + (size_t)(w * NTOK + row) * K2 + h * HEADD;
                #pragma unroll
                for (int nf = 0; nf < 4; nf++) {
                    const int d = nf * 8 + cb;
                    const float v0 = oacc[nf][hf * 2 + 0] * rs;
                    const float v1 = oacc[nf][hf * 2 + 1] * rs;
                    const __half h0 = __float2half_rn(v0);
                    const __half h1 = __float2half_rn(v1);
                    const __half l0 = __float2half_rn(v0 - __half2float(h0));
                    const __half l1 = __float2half_rn(v1 - __half2float(h1));
                    *(__half2*)(gp + d)       = __halves2half2(h0, h1);
                    *(__half2*)(gp + DIM + d) = __halves2half2(l0, l1);
                }
            }
        }
    }
}

// ---------------------------------------------------------------------------
// Launch: prep_all(1), bias_prep(2), gemm1(3), attn(4), gemm3(5)
// ---------------------------------------------------------------------------
extern "C" void kernel_launch(void* const* d_in, const int* in_sizes, int n_in,
                              void* d_out, int out_size)
{
    const float* x         = (const float*)d_in[0];
    const float* mask      = (const float*)d_in[1];
    const float* rel_table = (const float*)d_in[2];
    const float* qkv_w     = (const float*)d_in[3];
    const float* qkv_b     = (const float*)d_in[4];
    const float* proj_w    = (const float*)d_in[5];
    const float* proj_b    = (const float*)d_in[6];
    const int*   rel_idx   = (const int*)d_in[7];
    float*       out       = (float*)d_out;

    void *qkv_p, *x2_p, *attn2_p, *wq2_p, *wp2_p;
    cudaGetSymbolAddress(&qkv_p,   g_qkv);
    cudaGetSymbolAddress(&x2_p,    g_x2);
    cudaGetSymbolAddress(&attn2_p, g_attn2);
    cudaGetSymbolAddress(&wq2_p,   g_wqkv2);
    cudaGetSymbolAddress(&wp2_p,   g_wproj2);

    cudaFuncSetAttribute(gemm_mma,
                         cudaFuncAttributeMaxDynamicSharedMemorySize, GSMEM);
    cudaFuncSetAttribute(attn_tc_kernel,
                         cudaFuncAttributeMaxDynamicSharedMemorySize, ASMEM);

    // 1) merged splits
    {
        long t4x  = (long)MROWS * (DIM / 4);
        long t4wq = (long)QKV_COLS * (DIM / 4);
        long t4wp = (long)DIM * (DIM / 4);
        long tot  = t4x + t4wq + t4wp;
        prep_all<<<(unsigned)((tot + 255) / 256), 256>>>(
            x, qkv_w, proj_w,
            (__half*)x2_p, (__half*)wq2_p, (__half*)wp2_p,
            t4x, t4wq, t4wp);
    }
    // 2) bias precompute
    {
        int tot = NHEAD * NTOK * NTOK;
        bias_prep_kernel<<<(tot + 255) / 256, 256>>>(rel_table, rel_idx);
    }
    // 3) QKV GEMM
    {
        dim3 grid(QKV_COLS / 128, MROWS / 128);
        gemm_mma<<<grid, 256, GSMEM>>>(
            (const __half*)x2_p, (const __half*)wq2_p,
            qkv_b, (float*)qkv_p, QKV_COLS);
    }
    // 4) tensor-core attention
    {
        dim3 grid(NWIN, NHEAD);
        attn_tc_kernel<<<grid, 128, ASMEM>>>(mask);
    }
    // 5) projection GEMM
    {
        dim3 grid(DIM / 128, MROWS / 128);
        gemm_mma<<<grid, 256, GSMEM>>>(
            (const __half*)attn2_p, (const __half*)wp2_p,
            proj_b, out, DIM);
    }
}

// round 13
// speedup vs baseline: 1.2758x; 1.2758x over previous
#include <cuda_runtime.h>
#include <cuda_fp16.h>
#include <cstdint>
#include <cstddef>

// ---------------------------------------------------------------------------
// WindowAttention (Swin) on GB300 — Round 13.
// GEMMs: R8 config verbatim. Attention: tensor-core QK^T/AV with exp on MMA
// accumulator registers, quad-shuffle row sums, single block barrier,
// bias+mask pre-combined into padded global table.
// ---------------------------------------------------------------------------

#define NWIN      8192
#define NTOK      49
#define DIM       384
#define NHEAD     12
#define HEADD     32
#define NW_IMG    64
#define MROWS     (NWIN * NTOK)        // 401408
#define QKV_COLS  1152
#define K2        768                  // split K: hi | lo
#define SCALE_F   0.17677669529663687f
#define EXP_SHIFT 5.545177444479562f   // 8*ln2 headroom for fp16 P
#define BM_STRIDE 50                   // padded row stride (floats)
#define BM_SLICE  3200                 // 64 rows * 50

// Device scratch
__device__ float  g_qkv[(size_t)MROWS * QKV_COLS];
__device__ __half g_x2[(size_t)MROWS * K2];
__device__ __half g_attn2[(size_t)MROWS * K2];
__device__ __half g_wqkv2[(size_t)QKV_COLS * K2];
__device__ __half g_wproj2[(size_t)DIM * K2];
__device__ float  g_bm[(size_t)NW_IMG * NHEAD * BM_SLICE];  // bias+mask

// ---------------------------------------------------------------------------
// Helpers
// ---------------------------------------------------------------------------
__device__ __forceinline__ uint32_t smem_u32(const void* p) {
    uint32_t a;
    asm("{ .reg .u64 t; cvta.to.shared.u64 t, %1; cvt.u32.u64 %0, t; }"
        : "=r"(a) : "l"(p));
    return a;
}

__device__ __forceinline__ void cpa16(uint32_t dst, const void* src) {
    asm volatile("cp.async.cg.shared.global [%0], [%1], 16;"
                 :: "r"(dst), "l"(src));
}

__device__ __forceinline__ void ldsm_x4(uint32_t* r, uint32_t addr) {
    asm volatile("ldmatrix.sync.aligned.m8n8.x4.shared.b16 {%0,%1,%2,%3}, [%4];"
                 : "=r"(r[0]), "=r"(r[1]), "=r"(r[2]), "=r"(r[3])
                 : "r"(addr));
}

__device__ __forceinline__ void mma16816(float* d, const uint32_t* a,
                                         const uint32_t* b) {
    asm volatile(
        "mma.sync.aligned.m16n8k16.row.col.f32.f16.f16.f32 "
        "{%0,%1,%2,%3}, {%4,%5,%6,%7}, {%8,%9}, {%0,%1,%2,%3};"
        : "+f"(d[0]), "+f"(d[1]), "+f"(d[2]), "+f"(d[3])
        : "r"(a[0]), "r"(a[1]), "r"(a[2]), "r"(a[3]),
          "r"(b[0]), "r"(b[1]));
}

// exp(x) on the FMA pipe: 2^(x*log2e), deg-5 poly, rel err ~2.4e-6.
__device__ __forceinline__ float fast_exp(float x) {
    float t = fmaxf(x, -80.0f) * 1.442695040888963f;
    float r = rintf(t);
    float f = t - r;
    float p =             1.3333558e-3f;
    p = fmaf(p, f, 9.6181291e-3f);
    p = fmaf(p, f, 5.5504109e-2f);
    p = fmaf(p, f, 2.4022651e-1f);
    p = fmaf(p, f, 6.9314718e-1f);
    p = fmaf(p, f, 1.0f);
    int ri = (int)r;
    return __int_as_float(__float_as_int(p) + ri * 8388608);
}

// ---------------------------------------------------------------------------
// Merged prep kernel: splits x (act hi|lo), qkv_w and proj_w (wgt hi|hi).
// ---------------------------------------------------------------------------
__global__ void prep_all(const float* __restrict__ x,
                         const float* __restrict__ qkv_w,
                         const float* __restrict__ proj_w,
                         __half* __restrict__ x2,
                         __half* __restrict__ wq2,
                         __half* __restrict__ wp2,
                         long t4x, long t4wq, long t4wp)
{
    long idx = (long)blockIdx.x * blockDim.x + threadIdx.x;
    const float* in;
    __half* out;
    bool act;
    if (idx < t4x)                    { in = x;      out = x2;  act = true; }
    else if (idx < t4x + t4wq)        { idx -= t4x;  in = qkv_w; out = wq2; act = false; }
    else if (idx < t4x + t4wq + t4wp) { idx -= t4x + t4wq; in = proj_w; out = wp2; act = false; }
    else return;

    long r = idx / (DIM / 4);
    int  c4 = (int)(idx - r * (DIM / 4));
    float4 v = *((const float4*)(in + r * DIM) + c4);
    float a[4] = {v.x, v.y, v.z, v.w};
    __half hi[4], lo[4];
    #pragma unroll
    for (int i = 0; i < 4; i++) {
        hi[i] = __float2half_rn(a[i]);
        lo[i] = __float2half_rn(a[i] - __half2float(hi[i]));
    }
    __half2 h0 = __halves2half2(hi[0], hi[1]);
    __half2 h1 = __halves2half2(hi[2], hi[3]);
    __half2* s0 = (__half2*)(out + r * K2 + c4 * 4);
    __half2* s1 = (__half2*)(out + r * K2 + DIM + c4 * 4);
    s0[0] = h0; s0[1] = h1;
    if (act) {
        s1[0] = __halves2half2(lo[0], lo[1]);
        s1[1] = __halves2half2(lo[2], lo[3]);
    } else {
        s1[0] = h0; s1[1] = h1;
    }
}

// bias+mask combine: g_bm[(wm*12+h)][i*50+j] = bias[h][i][j] + mask[wm][i][j]
__global__ void bm_prep_kernel(const float* __restrict__ rel_table,
                               const int* __restrict__ rel_idx,
                               const float* __restrict__ mask)
{
    long t = (long)blockIdx.x * blockDim.x + threadIdx.x;
    if (t >= (long)NW_IMG * NHEAD * NTOK * NTOK) return;
    int slice = (int)(t / (NTOK * NTOK));
    int idx   = (int)(t - (long)slice * (NTOK * NTOK));
    int wm    = slice / NHEAD;
    int h     = slice - wm * NHEAD;
    int i     = idx / NTOK;
    int j     = idx - i * NTOK;
    g_bm[(size_t)slice * BM_SLICE + i * BM_STRIDE + j] =
        rel_table[rel_idx[idx] * NHEAD + h] + mask[(size_t)wm * (NTOK * NTOK) + idx];
}

// ---------------------------------------------------------------------------
// HMMA GEMM (R8 config, verbatim)
// ---------------------------------------------------------------------------
#define BKC       64
#define NCH       (K2 / BKC)
#define TILE_BYTES 16384
#define STAGE_BYTES (2 * TILE_BYTES)
#define GSMEM     (2 * STAGE_BYTES + 128)

__global__ __launch_bounds__(256, 2)
void gemm_mma(const __half* __restrict__ A,
              const __half* __restrict__ B,
              const float* __restrict__ bias,
              float* __restrict__ C, int Nn)
{
    extern __shared__ uint8_t smem_raw[];
    const int tid  = threadIdx.x;
    const int warp = tid >> 5;
    const int lane = tid & 31;

    uint32_t sraw  = smem_u32(smem_raw);
    uint32_t sbase = (sraw + 127u) & ~127u;

    const int m0 = blockIdx.y << 7;
    const int n0 = blockIdx.x << 7;

    const char* Ag = (const char*)(A + (size_t)m0 * K2);
    const char* Bg = (const char*)(B + (size_t)n0 * K2);
    uint32_t sw[4];
    size_t   go[4];
    #pragma unroll
    for (int i = 0; i < 4; i++) {
        int u = i * 256 + tid;
        int r = u >> 3, c = u & 7;
        sw[i] = (uint32_t)(r * 128 + ((c ^ (r & 7)) << 4));
        go[i] = (size_t)r * (K2 * 2) + (size_t)c * 16;
    }

    auto load_chunk = [&](int c, int s) {
        uint32_t ab = sbase + s * STAGE_BYTES;
        uint32_t bb = ab + TILE_BYTES;
        size_t koff = (size_t)c * 128;
        #pragma unroll
        for (int i = 0; i < 4; i++) {
            cpa16(ab + sw[i], Ag + go[i] + koff);
            cpa16(bb + sw[i], Bg + go[i] + koff);
        }
        asm volatile("cp.async.commit_group;" ::: "memory");
    };

    const int wm = warp & 1;
    const int wn = warp >> 1;
    const int l15 = lane & 15;
    const int lhi = lane >> 4;
    const int g8  = lane >> 3;
    const int l8  = lane & 7;

    int rA[4], rowOffA[4];
    #pragma unroll
    for (int mf = 0; mf < 4; mf++) {
        rA[mf] = wm * 64 + mf * 16 + l15;
        rowOffA[mf] = rA[mf] * 128;
    }
    int rB[2], rowOffB[2];
    #pragma unroll
    for (int p = 0; p < 2; p++) {
        rB[p] = wn * 32 + p * 16 + (g8 >> 1) * 8 + l8;
        rowOffB[p] = rB[p] * 128;
    }

    float acc[4][4][4];
    #pragma unroll
    for (int mf = 0; mf < 4; mf++)
        #pragma unroll
        for (int nf = 0; nf < 4; nf++)
            #pragma unroll
            for (int e = 0; e < 4; e++) acc[mf][nf][e] = 0.0f;

    load_chunk(0, 0);

    for (int c = 0; c < NCH; ++c) {
        if (c + 1 < NCH) {
            load_chunk(c + 1, (c + 1) & 1);
            asm volatile("cp.async.wait_group 1;" ::: "memory");
        } else {
            asm volatile("cp.async.wait_group 0;" ::: "memory");
        }
        __syncthreads();

        const uint32_t aT = sbase + (c & 1) * STAGE_BYTES;
        const uint32_t bT = aT + TILE_BYTES;

        #pragma unroll
        for (int ks = 0; ks < 4; ++ks) {
            uint32_t af[4][4];
            #pragma unroll
            for (int mf = 0; mf < 4; mf++) {
                const int c16 = ks * 2 + lhi;
                ldsm_x4(af[mf], aT + rowOffA[mf] +
                                ((c16 ^ (rA[mf] & 7)) << 4));
            }
            uint32_t bf[2][4];
            #pragma unroll
            for (int p = 0; p < 2; p++) {
                const int c16 = ks * 2 + (g8 & 1);
                ldsm_x4(bf[p], bT + rowOffB[p] +
                               ((c16 ^ (rB[p] & 7)) << 4));
            }
            #pragma unroll
            for (int mf = 0; mf < 4; mf++) {
                mma16816(acc[mf][0], af[mf], &bf[0][0]);
                mma16816(acc[mf][1], af[mf], &bf[0][2]);
                mma16816(acc[mf][2], af[mf], &bf[1][0]);
                mma16816(acc[mf][3], af[mf], &bf[1][2]);
            }
        }
        __syncthreads();
    }

    const int colBase = n0 + wn * 32 + 2 * (lane & 3);
    float2 b2[4];
    #pragma unroll
    for (int nf = 0; nf < 4; nf++)
        b2[nf] = *(const float2*)(bias + colBase + nf * 8);

    const int rowBase = m0 + wm * 64 + (lane >> 2);
    #pragma unroll
    for (int mf = 0; mf < 4; mf++) {
        const int r0 = rowBase + mf * 16;
        #pragma unroll
        for (int nf = 0; nf < 4; nf++) {
            const int col = colBase + nf * 8;
            float2 v0 = make_float2(acc[mf][nf][0] + b2[nf].x,
                                    acc[mf][nf][1] + b2[nf].y);
            float2 v1 = make_float2(acc[mf][nf][2] + b2[nf].x,
                                    acc[mf][nf][3] + b2[nf].y);
            *(float2*)(C + (size_t)r0 * Nn + col)       = v0;
            *(float2*)(C + (size_t)(r0 + 8) * Nn + col) = v1;
        }
    }
}

// ---------------------------------------------------------------------------
// Tensor-core attention v2: grid (NWIN, NHEAD), 128 threads (4 warps).
// smem: QA1 [hiQ|hiQ], QA2 [loQ|loQ], KB [hiK|loK] (64x128B each),
//       PH, PL (64x128B), VT (32x128B). One __syncthreads total.
// ---------------------------------------------------------------------------
#define A_QA1 0
#define A_QA2 8192
#define A_KB  16384
#define A_PH  24576
#define A_PL  32768
#define A_VT  40960
#define ASMEM (45056 + 128)

__device__ __forceinline__ uint32_t tile_addr(uint32_t tile, int row, int j) {
    return tile + row * 128 + ((((j >> 3) ^ (row & 7)) << 4) | ((j & 7) * 2));
}

__global__ __launch_bounds__(128)
void attn_tc_kernel()
{
    extern __shared__ uint8_t asm_raw[];
    const int tid  = threadIdx.x;
    const int warp = tid >> 5;
    const int lane = tid & 31;
    const int w    = blockIdx.x;
    const int h    = blockIdx.y;

    uint32_t sraw  = smem_u32(asm_raw);
    uint32_t sb    = (sraw + 127u) & ~127u;
    uint8_t* smem  = asm_raw + (sb - sraw);

    // ---- load qkv, build fp16 tiles (VT zero-padded inline, i to 64) ----
    const size_t base0 = (size_t)w * NTOK * QKV_COLS + h * HEADD;
    for (int idx = tid; idx < 64 * 8; idx += 128) {
        const int i = idx >> 3, c4 = idx & 7, d0 = c4 * 4;
        if (i < NTOK) {
            const float* gp = g_qkv + base0 + (size_t)i * QKV_COLS + d0;
            float4 qv = *(const float4*)gp;
            float4 kv = *(const float4*)(gp + 384);
            float4 vv = *(const float4*)(gp + 768);
            float qa[4] = {qv.x * SCALE_F, qv.y * SCALE_F,
                           qv.z * SCALE_F, qv.w * SCALE_F};
            float ka[4] = {kv.x, kv.y, kv.z, kv.w};
            float va[4] = {vv.x, vv.y, vv.z, vv.w};
            __half qh[4], ql[4], kh[4], kl[4];
            #pragma unroll
            for (int m = 0; m < 4; m++) {
                qh[m] = __float2half_rn(qa[m]);
                ql[m] = __float2half_rn(qa[m] - __half2float(qh[m]));
                kh[m] = __float2half_rn(ka[m]);
                kl[m] = __float2half_rn(ka[m] - __half2float(kh[m]));
            }
            uint32_t qhp[2] = {((uint32_t*)qh)[0], ((uint32_t*)qh)[1]};
            uint32_t qlp[2] = {((uint32_t*)ql)[0], ((uint32_t*)ql)[1]};
            uint32_t khp[2] = {((uint32_t*)kh)[0], ((uint32_t*)kh)[1]};
            uint32_t klp[2] = {((uint32_t*)kl)[0], ((uint32_t*)kl)[1]};
            *(uint2*)(smem + tile_addr(A_QA1, i, d0))      = make_uint2(qhp[0], qhp[1]);
            *(uint2*)(smem + tile_addr(A_QA1, i, d0 + 32)) = make_uint2(qhp[0], qhp[1]);
            *(uint2*)(smem + tile_addr(A_QA2, i, d0))      = make_uint2(qlp[0], qlp[1]);
            *(uint2*)(smem + tile_addr(A_QA2, i, d0 + 32)) = make_uint2(qlp[0], qlp[1]);
            *(uint2*)(smem + tile_addr(A_KB,  i, d0))      = make_uint2(khp[0], khp[1]);
            *(uint2*)(smem + tile_addr(A_KB,  i, d0 + 32)) = make_uint2(klp[0], klp[1]);
            #pragma unroll
            for (int m = 0; m < 4; m++)
                *(__half*)(smem + tile_addr(A_VT, d0 + m, i)) =
                    __float2half_rn(va[m]);
        } else {
            #pragma unroll
            for (int m = 0; m < 4; m++)
                *(__half*)(smem + tile_addr(A_VT, d0 + m, i)) = __half(0);
        }
    }
    __syncthreads();   // the only block-wide barrier

    const int l15 = lane & 15;
    const int lhi = lane >> 4;
    const int g8  = lane >> 3;
    const int l8  = lane & 7;

    // ---- QK^T: two passes (QA1, QA2) vs KB -> sacc registers ----
    float sacc[8][4];
    #pragma unroll
    for (int nf = 0; nf < 8; nf++)
        #pragma unroll
        for (int e = 0; e < 4; e++) sacc[nf][e] = 0.0f;
    {
        const int rA = warp * 16 + l15;
        int rB[4];
        #pragma unroll
        for (int p = 0; p < 4; p++) rB[p] = p * 16 + (g8 >> 1) * 8 + l8;

        #pragma unroll
        for (int pass = 0; pass < 2; pass++) {
            const uint32_t aTile = pass ? A_QA2 : A_QA1;
            #pragma unroll
            for (int ks = 0; ks < 4; ks++) {
                uint32_t af[4];
                const int c16a = ks * 2 + lhi;
                ldsm_x4(af, sb + aTile + rA * 128 + ((c16a ^ (rA & 7)) << 4));
                uint32_t bf[4][4];
                #pragma unroll
                for (int p = 0; p < 4; p++) {
                    const int c16b = ks * 2 + (g8 & 1);
                    ldsm_x4(bf[p], sb + A_KB + rB[p] * 128 +
                                   ((c16b ^ (rB[p] & 7)) << 4));
                }
                #pragma unroll
                for (int p = 0; p < 4; p++) {
                    mma16816(sacc[2 * p],     af, &bf[p][0]);
                    mma16816(sacc[2 * p + 1], af, &bf[p][2]);
                }
            }
        }
    }

    // ---- exp on registers + P store + quad-shuffle row sums (warp-local) ----
    const int r0 = warp * 16 + (lane >> 2);
    const int r1 = r0 + 8;
    const int cb = 2 * (lane & 3);
    float rsum0 = 0.0f, rsum1 = 0.0f;
    {
        const float* bm = g_bm +
            (size_t)((w & (NW_IMG - 1)) * NHEAD + h) * BM_SLICE;
        #pragma unroll
        for (int nf = 0; nf < 8; nf++) {
            const int c = nf * 8 + cb;
            float2 bm0 = *(const float2*)(bm + r0 * BM_STRIDE + c);
            float2 bm1 = *(const float2*)(bm + r1 * BM_STRIDE + c);
            float e00 = 0.0f, e01 = 0.0f, e10 = 0.0f, e11 = 0.0f;
            if (c < NTOK) {
                e00 = fast_exp(sacc[nf][0] + bm0.x - EXP_SHIFT);
                e10 = fast_exp(sacc[nf][2] + bm1.x - EXP_SHIFT);
                if (c + 1 < NTOK) {
                    e01 = fast_exp(sacc[nf][1] + bm0.y - EXP_SHIFT);
                    e11 = fast_exp(sacc[nf][3] + bm1.y - EXP_SHIFT);
                }
            }
            rsum0 += e00 + e01;
            rsum1 += e10 + e11;
            const __half h00 = __float2half_rn(e00);
            const __half h01 = __float2half_rn(e01);
            const __half h10 = __float2half_rn(e10);
            const __half h11 = __float2half_rn(e11);
            *(__half2*)(smem + tile_addr(A_PH, r0, c)) = __halves2half2(h00, h01);
            *(__half2*)(smem + tile_addr(A_PH, r1, c)) = __halves2half2(h10, h11);
            *(__half2*)(smem + tile_addr(A_PL, r0, c)) =
                __halves2half2(__float2half_rn(e00 - __half2float(h00)),
                               __float2half_rn(e01 - __half2float(h01)));
            *(__half2*)(smem + tile_addr(A_PL, r1, c)) =
                __halves2half2(__float2half_rn(e10 - __half2float(h10)),
                               __float2half_rn(e11 - __half2float(h11)));
        }
    }
    // reduce across the 4 lanes of each row group
    rsum0 += __shfl_xor_sync(0xFFFFFFFF, rsum0, 1);
    rsum0 += __shfl_xor_sync(0xFFFFFFFF, rsum0, 2);
    rsum1 += __shfl_xor_sync(0xFFFFFFFF, rsum1, 1);
    rsum1 += __shfl_xor_sync(0xFFFFFFFF, rsum1, 2);
    const float rs0 = 1.0f / rsum0;
    const float rs1 = 1.0f / rsum1;
    __syncwarp();

    // ---- AV: (PH then PL) @ VT -> O (warp-local A rows) ----
    float oacc[4][4];
    #pragma unroll
    for (int nf = 0; nf < 4; nf++)
        #pragma unroll
        for (int e = 0; e < 4; e++) oacc[nf][e] = 0.0f;
    {
        const int rA = warp * 16 + l15;
        int rB[2];
        #pragma unroll
        for (int p = 0; p < 2; p++) rB[p] = p * 16 + (g8 >> 1) * 8 + l8;

        #pragma unroll
        for (int pass = 0; pass < 2; pass++) {
            const uint32_t aTile = pass ? A_PL : A_PH;
            #pragma unroll
            for (int ks = 0; ks < 4; ks++) {
                uint32_t af[4];
                const int c16a = ks * 2 + lhi;
                ldsm_x4(af, sb + aTile + rA * 128 + ((c16a ^ (rA & 7)) << 4));
                uint32_t bf[2][4];
                #pragma unroll
                for (int p = 0; p < 2; p++) {
                    const int c16b = ks * 2 + (g8 & 1);
                    ldsm_x4(bf[p], sb + A_VT + rB[p] * 128 +
                                   ((c16b ^ (rB[p] & 7)) << 4));
                }
                mma16816(oacc[0], af, &bf[0][0]);
                mma16816(oacc[1], af, &bf[0][2]);
                mma16816(oacc[2], af, &bf[1][0]);
                mma16816(oacc[3], af, &bf[1][2]);
            }
        }
    }

    // ---- epilogue: scale by register rowsums, split fp16, store ----
    {
        #pragma unroll
        for (int hf = 0; hf < 2; hf++) {
            const int row = hf ? r1 : r0;
            const float rs = hf ? rs1 : rs0;
            if (row < NTOK) {
                __half* gp = g_attn2 + (size_t)(w * NTOK + row) * K2 + h * HEADD;
                #pragma unroll
                for (int nf = 0; nf < 4; nf++) {
                    const int d = nf * 8 + cb;
                    const float v0 = oacc[nf][hf * 2 + 0] * rs;
                    const float v1 = oacc[nf][hf * 2 + 1] * rs;
                    const __half h0 = __float2half_rn(v0);
                    const __half h1 = __float2half_rn(v1);
                    const __half l0 = __float2half_rn(v0 - __half2float(h0));
                    const __half l1 = __float2half_rn(v1 - __half2float(h1));
                    *(__half2*)(gp + d)       = __halves2half2(h0, h1);
                    *(__half2*)(gp + DIM + d) = __halves2half2(l0, l1);
                }
            }
        }
    }
}

// ---------------------------------------------------------------------------
// Launch: prep_all(1), bm_prep(2), gemm1(3), attn(4), gemm3(5)
// ---------------------------------------------------------------------------
extern "C" void kernel_launch(void* const* d_in, const int* in_sizes, int n_in,
                              void* d_out, int out_size)
{
    const float* x         = (const float*)d_in[0];
    const float* mask      = (const float*)d_in[1];
    const float* rel_table = (const float*)d_in[2];
    const float* qkv_w     = (const float*)d_in[3];
    const float* qkv_b     = (const float*)d_in[4];
    const float* proj_w    = (const float*)d_in[5];
    const float* proj_b    = (const float*)d_in[6];
    const int*   rel_idx   = (const int*)d_in[7];
    float*       out       = (float*)d_out;

    void *qkv_p, *x2_p, *attn2_p, *wq2_p, *wp2_p;
    cudaGetSymbolAddress(&qkv_p,   g_qkv);
    cudaGetSymbolAddress(&x2_p,    g_x2);
    cudaGetSymbolAddress(&attn2_p, g_attn2);
    cudaGetSymbolAddress(&wq2_p,   g_wqkv2);
    cudaGetSymbolAddress(&wp2_p,   g_wproj2);

    cudaFuncSetAttribute(gemm_mma,
                         cudaFuncAttributeMaxDynamicSharedMemorySize, GSMEM);
    cudaFuncSetAttribute(attn_tc_kernel,
                         cudaFuncAttributeMaxDynamicSharedMemorySize, ASMEM);

    // 1) merged splits
    {
        long t4x  = (long)MROWS * (DIM / 4);
        long t4wq = (long)QKV_COLS * (DIM / 4);
        long t4wp = (long)DIM * (DIM / 4);
        long tot  = t4x + t4wq + t4wp;
        prep_all<<<(unsigned)((tot + 255) / 256), 256>>>(
            x, qkv_w, proj_w,
            (__half*)x2_p, (__half*)wq2_p, (__half*)wp2_p,
            t4x, t4wq, t4wp);
    }
    // 2) bias+mask combine
    {
        long tot = (long)NW_IMG * NHEAD * NTOK * NTOK;
        bm_prep_kernel<<<(unsigned)((tot + 255) / 256), 256>>>(
            rel_table, rel_idx, mask);
    }
    // 3) QKV GEMM
    {
        dim3 grid(QKV_COLS / 128, MROWS / 128);
        gemm_mma<<<grid, 256, GSMEM>>>(
            (const __half*)x2_p, (const __half*)wq2_p,
            qkv_b, (float*)qkv_p, QKV_COLS);
    }
    // 4) tensor-core attention
    {
        dim3 grid(NWIN, NHEAD);
        attn_tc_kernel<<<grid, 128, ASMEM>>>();
    }
    // 5) projection GEMM
    {
        dim3 grid(DIM / 128, MROWS / 128);
        gemm_mma<<<grid, 256, GSMEM>>>(
            (const __half*)attn2_p, (const __half*)wp2_p,
            proj_b, out, DIM);
    }
}

// round 14
// speedup vs baseline: 1.2913x; 1.0121x over previous
#include <cuda_runtime.h>
#include <cuda_fp16.h>
#include <cstdint>
#include <cstddef>

// ---------------------------------------------------------------------------
// WindowAttention (Swin) on GB300 — Round 14.
// GEMMs/prep/bm: R13 verbatim. Attention: drop PL tile (P hi-only, error
// budget analysis in journal), hoist KB fragments across QK passes.
// ---------------------------------------------------------------------------

#define NWIN      8192
#define NTOK      49
#define DIM       384
#define NHEAD     12
#define HEADD     32
#define NW_IMG    64
#define MROWS     (NWIN * NTOK)        // 401408
#define QKV_COLS  1152
#define K2        768                  // split K: hi | lo
#define SCALE_F   0.17677669529663687f
#define EXP_SHIFT 5.545177444479562f   // 8*ln2 headroom for fp16 P
#define BM_STRIDE 50                   // padded row stride (floats)
#define BM_SLICE  3200                 // 64 rows * 50

// Device scratch
__device__ float  g_qkv[(size_t)MROWS * QKV_COLS];
__device__ __half g_x2[(size_t)MROWS * K2];
__device__ __half g_attn2[(size_t)MROWS * K2];
__device__ __half g_wqkv2[(size_t)QKV_COLS * K2];
__device__ __half g_wproj2[(size_t)DIM * K2];
__device__ float  g_bm[(size_t)NW_IMG * NHEAD * BM_SLICE];  // bias+mask

// ---------------------------------------------------------------------------
// Helpers
// ---------------------------------------------------------------------------
__device__ __forceinline__ uint32_t smem_u32(const void* p) {
    uint32_t a;
    asm("{ .reg .u64 t; cvta.to.shared.u64 t, %1; cvt.u32.u64 %0, t; }"
        : "=r"(a) : "l"(p));
    return a;
}

__device__ __forceinline__ void cpa16(uint32_t dst, const void* src) {
    asm volatile("cp.async.cg.shared.global [%0], [%1], 16;"
                 :: "r"(dst), "l"(src));
}

__device__ __forceinline__ void ldsm_x4(uint32_t* r, uint32_t addr) {
    asm volatile("ldmatrix.sync.aligned.m8n8.x4.shared.b16 {%0,%1,%2,%3}, [%4];"
                 : "=r"(r[0]), "=r"(r[1]), "=r"(r[2]), "=r"(r[3])
                 : "r"(addr));
}

__device__ __forceinline__ void mma16816(float* d, const uint32_t* a,
                                         const uint32_t* b) {
    asm volatile(
        "mma.sync.aligned.m16n8k16.row.col.f32.f16.f16.f32 "
        "{%0,%1,%2,%3}, {%4,%5,%6,%7}, {%8,%9}, {%0,%1,%2,%3};"
        : "+f"(d[0]), "+f"(d[1]), "+f"(d[2]), "+f"(d[3])
        : "r"(a[0]), "r"(a[1]), "r"(a[2]), "r"(a[3]),
          "r"(b[0]), "r"(b[1]));
}

// exp(x) on the FMA pipe: 2^(x*log2e), deg-5 poly, rel err ~2.4e-6.
__device__ __forceinline__ float fast_exp(float x) {
    float t = fmaxf(x, -80.0f) * 1.442695040888963f;
    float r = rintf(t);
    float f = t - r;
    float p =             1.3333558e-3f;
    p = fmaf(p, f, 9.6181291e-3f);
    p = fmaf(p, f, 5.5504109e-2f);
    p = fmaf(p, f, 2.4022651e-1f);
    p = fmaf(p, f, 6.9314718e-1f);
    p = fmaf(p, f, 1.0f);
    int ri = (int)r;
    return __int_as_float(__float_as_int(p) + ri * 8388608);
}

// ---------------------------------------------------------------------------
// Merged prep kernel: splits x (act hi|lo), qkv_w and proj_w (wgt hi|hi).
// ---------------------------------------------------------------------------
__global__ void prep_all(const float* __restrict__ x,
                         const float* __restrict__ qkv_w,
                         const float* __restrict__ proj_w,
                         __half* __restrict__ x2,
                         __half* __restrict__ wq2,
                         __half* __restrict__ wp2,
                         long t4x, long t4wq, long t4wp)
{
    long idx = (long)blockIdx.x * blockDim.x + threadIdx.x;
    const float* in;
    __half* out;
    bool act;
    if (idx < t4x)                    { in = x;      out = x2;  act = true; }
    else if (idx < t4x + t4wq)        { idx -= t4x;  in = qkv_w; out = wq2; act = false; }
    else if (idx < t4x + t4wq + t4wp) { idx -= t4x + t4wq; in = proj_w; out = wp2; act = false; }
    else return;

    long r = idx / (DIM / 4);
    int  c4 = (int)(idx - r * (DIM / 4));
    float4 v = *((const float4*)(in + r * DIM) + c4);
    float a[4] = {v.x, v.y, v.z, v.w};
    __half hi[4], lo[4];
    #pragma unroll
    for (int i = 0; i < 4; i++) {
        hi[i] = __float2half_rn(a[i]);
        lo[i] = __float2half_rn(a[i] - __half2float(hi[i]));
    }
    __half2 h0 = __halves2half2(hi[0], hi[1]);
    __half2 h1 = __halves2half2(hi[2], hi[3]);
    __half2* s0 = (__half2*)(out + r * K2 + c4 * 4);
    __half2* s1 = (__half2*)(out + r * K2 + DIM + c4 * 4);
    s0[0] = h0; s0[1] = h1;
    if (act) {
        s1[0] = __halves2half2(lo[0], lo[1]);
        s1[1] = __halves2half2(lo[2], lo[3]);
    } else {
        s1[0] = h0; s1[1] = h1;
    }
}

// bias+mask combine
__global__ void bm_prep_kernel(const float* __restrict__ rel_table,
                               const int* __restrict__ rel_idx,
                               const float* __restrict__ mask)
{
    long t = (long)blockIdx.x * blockDim.x + threadIdx.x;
    if (t >= (long)NW_IMG * NHEAD * NTOK * NTOK) return;
    int slice = (int)(t / (NTOK * NTOK));
    int idx   = (int)(t - (long)slice * (NTOK * NTOK));
    int wm    = slice / NHEAD;
    int h     = slice - wm * NHEAD;
    int i     = idx / NTOK;
    int j     = idx - i * NTOK;
    g_bm[(size_t)slice * BM_SLICE + i * BM_STRIDE + j] =
        rel_table[rel_idx[idx] * NHEAD + h] + mask[(size_t)wm * (NTOK * NTOK) + idx];
}

// ---------------------------------------------------------------------------
// HMMA GEMM (R8 config, verbatim)
// ---------------------------------------------------------------------------
#define BKC       64
#define NCH       (K2 / BKC)
#define TILE_BYTES 16384
#define STAGE_BYTES (2 * TILE_BYTES)
#define GSMEM     (2 * STAGE_BYTES + 128)

__global__ __launch_bounds__(256, 2)
void gemm_mma(const __half* __restrict__ A,
              const __half* __restrict__ B,
              const float* __restrict__ bias,
              float* __restrict__ C, int Nn)
{
    extern __shared__ uint8_t smem_raw[];
    const int tid  = threadIdx.x;
    const int warp = tid >> 5;
    const int lane = tid & 31;

    uint32_t sraw  = smem_u32(smem_raw);
    uint32_t sbase = (sraw + 127u) & ~127u;

    const int m0 = blockIdx.y << 7;
    const int n0 = blockIdx.x << 7;

    const char* Ag = (const char*)(A + (size_t)m0 * K2);
    const char* Bg = (const char*)(B + (size_t)n0 * K2);
    uint32_t sw[4];
    size_t   go[4];
    #pragma unroll
    for (int i = 0; i < 4; i++) {
        int u = i * 256 + tid;
        int r = u >> 3, c = u & 7;
        sw[i] = (uint32_t)(r * 128 + ((c ^ (r & 7)) << 4));
        go[i] = (size_t)r * (K2 * 2) + (size_t)c * 16;
    }

    auto load_chunk = [&](int c, int s) {
        uint32_t ab = sbase + s * STAGE_BYTES;
        uint32_t bb = ab + TILE_BYTES;
        size_t koff = (size_t)c * 128;
        #pragma unroll
        for (int i = 0; i < 4; i++) {
            cpa16(ab + sw[i], Ag + go[i] + koff);
            cpa16(bb + sw[i], Bg + go[i] + koff);
        }
        asm volatile("cp.async.commit_group;" ::: "memory");
    };

    const int wm = warp & 1;
    const int wn = warp >> 1;
    const int l15 = lane & 15;
    const int lhi = lane >> 4;
    const int g8  = lane >> 3;
    const int l8  = lane & 7;

    int rA[4], rowOffA[4];
    #pragma unroll
    for (int mf = 0; mf < 4; mf++) {
        rA[mf] = wm * 64 + mf * 16 + l15;
        rowOffA[mf] = rA[mf] * 128;
    }
    int rB[2], rowOffB[2];
    #pragma unroll
    for (int p = 0; p < 2; p++) {
        rB[p] = wn * 32 + p * 16 + (g8 >> 1) * 8 + l8;
        rowOffB[p] = rB[p] * 128;
    }

    float acc[4][4][4];
    #pragma unroll
    for (int mf = 0; mf < 4; mf++)
        #pragma unroll
        for (int nf = 0; nf < 4; nf++)
            #pragma unroll
            for (int e = 0; e < 4; e++) acc[mf][nf][e] = 0.0f;

    load_chunk(0, 0);

    for (int c = 0; c < NCH; ++c) {
        if (c + 1 < NCH) {
            load_chunk(c + 1, (c + 1) & 1);
            asm volatile("cp.async.wait_group 1;" ::: "memory");
        } else {
            asm volatile("cp.async.wait_group 0;" ::: "memory");
        }
        __syncthreads();

        const uint32_t aT = sbase + (c & 1) * STAGE_BYTES;
        const uint32_t bT = aT + TILE_BYTES;

        #pragma unroll
        for (int ks = 0; ks < 4; ++ks) {
            uint32_t af[4][4];
            #pragma unroll
            for (int mf = 0; mf < 4; mf++) {
                const int c16 = ks * 2 + lhi;
                ldsm_x4(af[mf], aT + rowOffA[mf] +
                                ((c16 ^ (rA[mf] & 7)) << 4));
            }
            uint32_t bf[2][4];
            #pragma unroll
            for (int p = 0; p < 2; p++) {
                const int c16 = ks * 2 + (g8 & 1);
                ldsm_x4(bf[p], bT + rowOffB[p] +
                               ((c16 ^ (rB[p] & 7)) << 4));
            }
            #pragma unroll
            for (int mf = 0; mf < 4; mf++) {
                mma16816(acc[mf][0], af[mf], &bf[0][0]);
                mma16816(acc[mf][1], af[mf], &bf[0][2]);
                mma16816(acc[mf][2], af[mf], &bf[1][0]);
                mma16816(acc[mf][3], af[mf], &bf[1][2]);
            }
        }
        __syncthreads();
    }

    const int colBase = n0 + wn * 32 + 2 * (lane & 3);
    float2 b2[4];
    #pragma unroll
    for (int nf = 0; nf < 4; nf++)
        b2[nf] = *(const float2*)(bias + colBase + nf * 8);

    const int rowBase = m0 + wm * 64 + (lane >> 2);
    #pragma unroll
    for (int mf = 0; mf < 4; mf++) {
        const int r0 = rowBase + mf * 16;
        #pragma unroll
        for (int nf = 0; nf < 4; nf++) {
            const int col = colBase + nf * 8;
            float2 v0 = make_float2(acc[mf][nf][0] + b2[nf].x,
                                    acc[mf][nf][1] + b2[nf].y);
            float2 v1 = make_float2(acc[mf][nf][2] + b2[nf].x,
                                    acc[mf][nf][3] + b2[nf].y);
            *(float2*)(C + (size_t)r0 * Nn + col)       = v0;
            *(float2*)(C + (size_t)(r0 + 8) * Nn + col) = v1;
        }
    }
}

// ---------------------------------------------------------------------------
// Tensor-core attention v3: grid (NWIN, NHEAD), 128 threads (4 warps).
// smem: QA1, QA2, KB, PH (64x128B each), VT (32x128B). One __syncthreads.
// P stored hi-only (fp16); KB fragments hoisted across QK passes.
// ---------------------------------------------------------------------------
#define A_QA1 0
#define A_QA2 8192
#define A_KB  16384
#define A_PH  24576
#define A_VT  32768
#define ASMEM (36864 + 128)

__device__ __forceinline__ uint32_t tile_addr(uint32_t tile, int row, int j) {
    return tile + row * 128 + ((((j >> 3) ^ (row & 7)) << 4) | ((j & 7) * 2));
}

__global__ __launch_bounds__(128)
void attn_tc_kernel()
{
    extern __shared__ uint8_t asm_raw[];
    const int tid  = threadIdx.x;
    const int warp = tid >> 5;
    const int lane = tid & 31;
    const int w    = blockIdx.x;
    const int h    = blockIdx.y;

    uint32_t sraw  = smem_u32(asm_raw);
    uint32_t sb    = (sraw + 127u) & ~127u;
    uint8_t* smem  = asm_raw + (sb - sraw);

    // ---- load qkv, build fp16 tiles (VT zero-padded inline, i to 64) ----
    const size_t base0 = (size_t)w * NTOK * QKV_COLS + h * HEADD;
    for (int idx = tid; idx < 64 * 8; idx += 128) {
        const int i = idx >> 3, c4 = idx & 7, d0 = c4 * 4;
        if (i < NTOK) {
            const float* gp = g_qkv + base0 + (size_t)i * QKV_COLS + d0;
            float4 qv = *(const float4*)gp;
            float4 kv = *(const float4*)(gp + 384);
            float4 vv = *(const float4*)(gp + 768);
            float qa[4] = {qv.x * SCALE_F, qv.y * SCALE_F,
                           qv.z * SCALE_F, qv.w * SCALE_F};
            float ka[4] = {kv.x, kv.y, kv.z, kv.w};
            float va[4] = {vv.x, vv.y, vv.z, vv.w};
            __half qh[4], ql[4], kh[4], kl[4];
            #pragma unroll
            for (int m = 0; m < 4; m++) {
                qh[m] = __float2half_rn(qa[m]);
                ql[m] = __float2half_rn(qa[m] - __half2float(qh[m]));
                kh[m] = __float2half_rn(ka[m]);
                kl[m] = __float2half_rn(ka[m] - __half2float(kh[m]));
            }
            uint32_t qhp[2] = {((uint32_t*)qh)[0], ((uint32_t*)qh)[1]};
            uint32_t qlp[2] = {((uint32_t*)ql)[0], ((uint32_t*)ql)[1]};
            uint32_t khp[2] = {((uint32_t*)kh)[0], ((uint32_t*)kh)[1]};
            uint32_t klp[2] = {((uint32_t*)kl)[0], ((uint32_t*)kl)[1]};
            *(uint2*)(smem + tile_addr(A_QA1, i, d0))      = make_uint2(qhp[0], qhp[1]);
            *(uint2*)(smem + tile_addr(A_QA1, i, d0 + 32)) = make_uint2(qhp[0], qhp[1]);
            *(uint2*)(smem + tile_addr(A_QA2, i, d0))      = make_uint2(qlp[0], qlp[1]);
            *(uint2*)(smem + tile_addr(A_QA2, i, d0 + 32)) = make_uint2(qlp[0], qlp[1]);
            *(uint2*)(smem + tile_addr(A_KB,  i, d0))      = make_uint2(khp[0], khp[1]);
            *(uint2*)(smem + tile_addr(A_KB,  i, d0 + 32)) = make_uint2(klp[0], klp[1]);
            #pragma unroll
            for (int m = 0; m < 4; m++)
                *(__half*)(smem + tile_addr(A_VT, d0 + m, i)) =
                    __float2half_rn(va[m]);
        } else {
            #pragma unroll
            for (int m = 0; m < 4; m++)
                *(__half*)(smem + tile_addr(A_VT, d0 + m, i)) = __half(0);
        }
    }
    __syncthreads();   // the only block-wide barrier

    const int l15 = lane & 15;
    const int lhi = lane >> 4;
    const int g8  = lane >> 3;
    const int l8  = lane & 7;

    // ---- QK^T: ks-outer, KB fragments loaded once per ks, both QA passes ----
    float sacc[8][4];
    #pragma unroll
    for (int nf = 0; nf < 8; nf++)
        #pragma unroll
        for (int e = 0; e < 4; e++) sacc[nf][e] = 0.0f;
    {
        const int rA = warp * 16 + l15;
        int rB[4];
        #pragma unroll
        for (int p = 0; p < 4; p++) rB[p] = p * 16 + (g8 >> 1) * 8 + l8;

        #pragma unroll
        for (int ks = 0; ks < 4; ks++) {
            const int c16a = ks * 2 + lhi;
            const uint32_t aoff = rA * 128 + ((c16a ^ (rA & 7)) << 4);
            uint32_t af1[4], af2[4];
            ldsm_x4(af1, sb + A_QA1 + aoff);
            ldsm_x4(af2, sb + A_QA2 + aoff);
            uint32_t bf[4][4];
            #pragma unroll
            for (int p = 0; p < 4; p++) {
                const int c16b = ks * 2 + (g8 & 1);
                ldsm_x4(bf[p], sb + A_KB + rB[p] * 128 +
                               ((c16b ^ (rB[p] & 7)) << 4));
            }
            #pragma unroll
            for (int p = 0; p < 4; p++) {
                mma16816(sacc[2 * p],     af1, &bf[p][0]);
                mma16816(sacc[2 * p + 1], af1, &bf[p][2]);
                mma16816(sacc[2 * p],     af2, &bf[p][0]);
                mma16816(sacc[2 * p + 1], af2, &bf[p][2]);
            }
        }
    }

    // ---- exp on registers + P store (hi only) + quad-shuffle row sums ----
    const int r0 = warp * 16 + (lane >> 2);
    const int r1 = r0 + 8;
    const int cb = 2 * (lane & 3);
    float rsum0 = 0.0f, rsum1 = 0.0f;
    {
        const float* bm = g_bm +
            (size_t)((w & (NW_IMG - 1)) * NHEAD + h) * BM_SLICE;
        #pragma unroll
        for (int nf = 0; nf < 8; nf++) {
            const int c = nf * 8 + cb;
            float2 bm0 = *(const float2*)(bm + r0 * BM_STRIDE + c);
            float2 bm1 = *(const float2*)(bm + r1 * BM_STRIDE + c);
            float e00 = 0.0f, e01 = 0.0f, e10 = 0.0f, e11 = 0.0f;
            if (c < NTOK) {
                e00 = fast_exp(sacc[nf][0] + bm0.x - EXP_SHIFT);
                e10 = fast_exp(sacc[nf][2] + bm1.x - EXP_SHIFT);
                if (c + 1 < NTOK) {
                    e01 = fast_exp(sacc[nf][1] + bm0.y - EXP_SHIFT);
                    e11 = fast_exp(sacc[nf][3] + bm1.y - EXP_SHIFT);
                }
            }
            rsum0 += e00 + e01;
            rsum1 += e10 + e11;
            *(__half2*)(smem + tile_addr(A_PH, r0, c)) =
                __halves2half2(__float2half_rn(e00), __float2half_rn(e01));
            *(__half2*)(smem + tile_addr(A_PH, r1, c)) =
                __halves2half2(__float2half_rn(e10), __float2half_rn(e11));
        }
    }
    rsum0 += __shfl_xor_sync(0xFFFFFFFF, rsum0, 1);
    rsum0 += __shfl_xor_sync(0xFFFFFFFF, rsum0, 2);
    rsum1 += __shfl_xor_sync(0xFFFFFFFF, rsum1, 1);
    rsum1 += __shfl_xor_sync(0xFFFFFFFF, rsum1, 2);
    const float rs0 = 1.0f / rsum0;
    const float rs1 = 1.0f / rsum1;
    __syncwarp();

    // ---- AV: PH @ VT -> O (single pass) ----
    float oacc[4][4];
    #pragma unroll
    for (int nf = 0; nf < 4; nf++)
        #pragma unroll
        for (int e = 0; e < 4; e++) oacc[nf][e] = 0.0f;
    {
        const int rA = warp * 16 + l15;
        int rB[2];
        #pragma unroll
        for (int p = 0; p < 2; p++) rB[p] = p * 16 + (g8 >> 1) * 8 + l8;

        #pragma unroll
        for (int ks = 0; ks < 4; ks++) {
            uint32_t af[4];
            const int c16a = ks * 2 + lhi;
            ldsm_x4(af, sb + A_PH + rA * 128 + ((c16a ^ (rA & 7)) << 4));
            uint32_t bf[2][4];
            #pragma unroll
            for (int p = 0; p < 2; p++) {
                const int c16b = ks * 2 + (g8 & 1);
                ldsm_x4(bf[p], sb + A_VT + rB[p] * 128 +
                               ((c16b ^ (rB[p] & 7)) << 4));
            }
            mma16816(oacc[0], af, &bf[0][0]);
            mma16816(oacc[1], af, &bf[0][2]);
            mma16816(oacc[2], af, &bf[1][0]);
            mma16816(oacc[3], af, &bf[1][2]);
        }
    }

    // ---- epilogue: scale by register rowsums, split fp16, store ----
    {
        #pragma unroll
        for (int hf = 0; hf < 2; hf++) {
            const int row = hf ? r1 : r0;
            const float rs = hf ? rs1 : rs0;
            if (row < NTOK) {
                __half* gp = g_attn2 + (size_t)(w * NTOK + row) * K2 + h * HEADD;
                #pragma unroll
                for (int nf = 0; nf < 4; nf++) {
                    const int d = nf * 8 + cb;
                    const float v0 = oacc[nf][hf * 2 + 0] * rs;
                    const float v1 = oacc[nf][hf * 2 + 1] * rs;
                    const __half h0 = __float2half_rn(v0);
                    const __half h1 = __float2half_rn(v1);
                    const __half l0 = __float2half_rn(v0 - __half2float(h0));
                    const __half l1 = __float2half_rn(v1 - __half2float(h1));
                    *(__half2*)(gp + d)       = __halves2half2(h0, h1);
                    *(__half2*)(gp + DIM + d) = __halves2half2(l0, l1);
                }
            }
        }
    }
}

// ---------------------------------------------------------------------------
// Launch: prep_all(1), bm_prep(2), gemm1(3), attn(4), gemm3(5)
// ---------------------------------------------------------------------------
extern "C" void kernel_launch(void* const* d_in, const int* in_sizes, int n_in,
                              void* d_out, int out_size)
{
    const float* x         = (const float*)d_in[0];
    const float* mask      = (const float*)d_in[1];
    const float* rel_table = (const float*)d_in[2];
    const float* qkv_w     = (const float*)d_in[3];
    const float* qkv_b     = (const float*)d_in[4];
    const float* proj_w    = (const float*)d_in[5];
    const float* proj_b    = (const float*)d_in[6];
    const int*   rel_idx   = (const int*)d_in[7];
    float*       out       = (float*)d_out;

    void *qkv_p, *x2_p, *attn2_p, *wq2_p, *wp2_p;
    cudaGetSymbolAddress(&qkv_p,   g_qkv);
    cudaGetSymbolAddress(&x2_p,    g_x2);
    cudaGetSymbolAddress(&attn2_p, g_attn2);
    cudaGetSymbolAddress(&wq2_p,   g_wqkv2);
    cudaGetSymbolAddress(&wp2_p,   g_wproj2);

    cudaFuncSetAttribute(gemm_mma,
                         cudaFuncAttributeMaxDynamicSharedMemorySize, GSMEM);
    cudaFuncSetAttribute(attn_tc_kernel,
                         cudaFuncAttributeMaxDynamicSharedMemorySize, ASMEM);

    // 1) merged splits
    {
        long t4x  = (long)MROWS * (DIM / 4);
        long t4wq = (long)QKV_COLS * (DIM / 4);
        long t4wp = (long)DIM * (DIM / 4);
        long tot  = t4x + t4wq + t4wp;
        prep_all<<<(unsigned)((tot + 255) / 256), 256>>>(
            x, qkv_w, proj_w,
            (__half*)x2_p, (__half*)wq2_p, (__half*)wp2_p,
            t4x, t4wq, t4wp);
    }
    // 2) bias+mask combine
    {
        long tot = (long)NW_IMG * NHEAD * NTOK * NTOK;
        bm_prep_kernel<<<(unsigned)((tot + 255) / 256), 256>>>(
            rel_table, rel_idx, mask);
    }
    // 3) QKV GEMM
    {
        dim3 grid(QKV_COLS / 128, MROWS / 128);
        gemm_mma<<<grid, 256, GSMEM>>>(
            (const __half*)x2_p, (const __half*)wq2_p,
            qkv_b, (float*)qkv_p, QKV_COLS);
    }
    // 4) tensor-core attention
    {
        dim3 grid(NWIN, NHEAD);
        attn_tc_kernel<<<grid, 128, ASMEM>>>();
    }
    // 5) projection GEMM
    {
        dim3 grid(DIM / 128, MROWS / 128);
        gemm_mma<<<grid, 256, GSMEM>>>(
            (const __half*)attn2_p, (const __half*)wp2_p,
            proj_b, out, DIM);
    }
}

// round 15
// speedup vs baseline: 1.8740x; 1.4512x over previous
#include <cuda_runtime.h>
#include <cuda_fp16.h>
#include <cstdint>
#include <cstddef>

// ---------------------------------------------------------------------------
// WindowAttention (Swin) on GB300 — Round 15.
// Plain fp16 GEMMs (K=384, no K-concat split): qkv error grows ~1.4e-4 RMS,
// attention keeps its internal q/k hi/lo split so scores stay accurate.
// Attention epilogue stores hi-only fp16. Everything else R14.
// ---------------------------------------------------------------------------

#define NWIN      8192
#define NTOK      49
#define DIM       384
#define NHEAD     12
#define HEADD     32
#define NW_IMG    64
#define MROWS     (NWIN * NTOK)        // 401408
#define QKV_COLS  1152
#define KG        384                  // GEMM K (plain fp16)
#define SCALE_F   0.17677669529663687f
#define EXP_SHIFT 5.545177444479562f   // 8*ln2 headroom for fp16 P
#define BM_STRIDE 50                   // padded row stride (floats)
#define BM_SLICE  3200                 // 64 rows * 50

// Device scratch
__device__ float  g_qkv[(size_t)MROWS * QKV_COLS];
__device__ __half g_x2[(size_t)MROWS * KG];
__device__ __half g_attn2[(size_t)MROWS * KG];
__device__ __half g_wqkv2[(size_t)QKV_COLS * KG];
__device__ __half g_wproj2[(size_t)DIM * KG];
__device__ float  g_bm[(size_t)NW_IMG * NHEAD * BM_SLICE];  // bias+mask

// ---------------------------------------------------------------------------
// Helpers
// ---------------------------------------------------------------------------
__device__ __forceinline__ uint32_t smem_u32(const void* p) {
    uint32_t a;
    asm("{ .reg .u64 t; cvta.to.shared.u64 t, %1; cvt.u32.u64 %0, t; }"
        : "=r"(a) : "l"(p));
    return a;
}

__device__ __forceinline__ void cpa16(uint32_t dst, const void* src) {
    asm volatile("cp.async.cg.shared.global [%0], [%1], 16;"
                 :: "r"(dst), "l"(src));
}

__device__ __forceinline__ void ldsm_x4(uint32_t* r, uint32_t addr) {
    asm volatile("ldmatrix.sync.aligned.m8n8.x4.shared.b16 {%0,%1,%2,%3}, [%4];"
                 : "=r"(r[0]), "=r"(r[1]), "=r"(r[2]), "=r"(r[3])
                 : "r"(addr));
}

__device__ __forceinline__ void mma16816(float* d, const uint32_t* a,
                                         const uint32_t* b) {
    asm volatile(
        "mma.sync.aligned.m16n8k16.row.col.f32.f16.f16.f32 "
        "{%0,%1,%2,%3}, {%4,%5,%6,%7}, {%8,%9}, {%0,%1,%2,%3};"
        : "+f"(d[0]), "+f"(d[1]), "+f"(d[2]), "+f"(d[3])
        : "r"(a[0]), "r"(a[1]), "r"(a[2]), "r"(a[3]),
          "r"(b[0]), "r"(b[1]));
}

// exp(x) on the FMA pipe: 2^(x*log2e), deg-5 poly, rel err ~2.4e-6.
__device__ __forceinline__ float fast_exp(float x) {
    float t = fmaxf(x, -80.0f) * 1.442695040888963f;
    float r = rintf(t);
    float f = t - r;
    float p =             1.3333558e-3f;
    p = fmaf(p, f, 9.6181291e-3f);
    p = fmaf(p, f, 5.5504109e-2f);
    p = fmaf(p, f, 2.4022651e-1f);
    p = fmaf(p, f, 6.9314718e-1f);
    p = fmaf(p, f, 1.0f);
    int ri = (int)r;
    return __int_as_float(__float_as_int(p) + ri * 8388608);
}

// ---------------------------------------------------------------------------
// Prep kernel: fp32 [rows][384] -> fp16 [rows][384] for x, qkv_w, proj_w.
// ---------------------------------------------------------------------------
__global__ void prep_all(const float* __restrict__ x,
                         const float* __restrict__ qkv_w,
                         const float* __restrict__ proj_w,
                         __half* __restrict__ x2,
                         __half* __restrict__ wq2,
                         __half* __restrict__ wp2,
                         long t4x, long t4wq, long t4wp)
{
    long idx = (long)blockIdx.x * blockDim.x + threadIdx.x;
    const float* in;
    __half* out;
    if (idx < t4x)                    { in = x;      out = x2; }
    else if (idx < t4x + t4wq)        { idx -= t4x;  in = qkv_w; out = wq2; }
    else if (idx < t4x + t4wq + t4wp) { idx -= t4x + t4wq; in = proj_w; out = wp2; }
    else return;

    float4 v = *((const float4*)in + idx);
    __half2* o = (__half2*)out + idx * 2;
    o[0] = __halves2half2(__float2half_rn(v.x), __float2half_rn(v.y));
    o[1] = __halves2half2(__float2half_rn(v.z), __float2half_rn(v.w));
}

// bias+mask combine
__global__ void bm_prep_kernel(const float* __restrict__ rel_table,
                               const int* __restrict__ rel_idx,
                               const float* __restrict__ mask)
{
    long t = (long)blockIdx.x * blockDim.x + threadIdx.x;
    if (t >= (long)NW_IMG * NHEAD * NTOK * NTOK) return;
    int slice = (int)(t / (NTOK * NTOK));
    int idx   = (int)(t - (long)slice * (NTOK * NTOK));
    int wm    = slice / NHEAD;
    int h     = slice - wm * NHEAD;
    int i     = idx / NTOK;
    int j     = idx - i * NTOK;
    g_bm[(size_t)slice * BM_SLICE + i * BM_STRIDE + j] =
        rel_table[rel_idx[idx] * NHEAD + h] + mask[(size_t)wm * (NTOK * NTOK) + idx];
}

// ---------------------------------------------------------------------------
// HMMA GEMM (R8 structure, K=384): C = A2 @ B2^T + bias  (fp16 -> fp32)
// 128x128 tile, BK=64, XOR-8 swizzle, 2-stage cp.async, 8 warps 64x32.
// ---------------------------------------------------------------------------
#define BKC       64
#define NCH       (KG / BKC)            // 6
#define TILE_BYTES 16384
#define STAGE_BYTES (2 * TILE_BYTES)
#define GSMEM     (2 * STAGE_BYTES + 128)

__global__ __launch_bounds__(256, 2)
void gemm_mma(const __half* __restrict__ A,
              const __half* __restrict__ B,
              const float* __restrict__ bias,
              float* __restrict__ C, int Nn)
{
    extern __shared__ uint8_t smem_raw[];
    const int tid  = threadIdx.x;
    const int warp = tid >> 5;
    const int lane = tid & 31;

    uint32_t sraw  = smem_u32(smem_raw);
    uint32_t sbase = (sraw + 127u) & ~127u;

    const int m0 = blockIdx.y << 7;
    const int n0 = blockIdx.x << 7;

    const char* Ag = (const char*)(A + (size_t)m0 * KG);
    const char* Bg = (const char*)(B + (size_t)n0 * KG);
    uint32_t sw[4];
    size_t   go[4];
    #pragma unroll
    for (int i = 0; i < 4; i++) {
        int u = i * 256 + tid;
        int r = u >> 3, c = u & 7;
        sw[i] = (uint32_t)(r * 128 + ((c ^ (r & 7)) << 4));
        go[i] = (size_t)r * (KG * 2) + (size_t)c * 16;
    }

    auto load_chunk = [&](int c, int s) {
        uint32_t ab = sbase + s * STAGE_BYTES;
        uint32_t bb = ab + TILE_BYTES;
        size_t koff = (size_t)c * 128;
        #pragma unroll
        for (int i = 0; i < 4; i++) {
            cpa16(ab + sw[i], Ag + go[i] + koff);
            cpa16(bb + sw[i], Bg + go[i] + koff);
        }
        asm volatile("cp.async.commit_group;" ::: "memory");
    };

    const int wm = warp & 1;
    const int wn = warp >> 1;
    const int l15 = lane & 15;
    const int lhi = lane >> 4;
    const int g8  = lane >> 3;
    const int l8  = lane & 7;

    int rA[4], rowOffA[4];
    #pragma unroll
    for (int mf = 0; mf < 4; mf++) {
        rA[mf] = wm * 64 + mf * 16 + l15;
        rowOffA[mf] = rA[mf] * 128;
    }
    int rB[2], rowOffB[2];
    #pragma unroll
    for (int p = 0; p < 2; p++) {
        rB[p] = wn * 32 + p * 16 + (g8 >> 1) * 8 + l8;
        rowOffB[p] = rB[p] * 128;
    }

    float acc[4][4][4];
    #pragma unroll
    for (int mf = 0; mf < 4; mf++)
        #pragma unroll
        for (int nf = 0; nf < 4; nf++)
            #pragma unroll
            for (int e = 0; e < 4; e++) acc[mf][nf][e] = 0.0f;

    load_chunk(0, 0);

    for (int c = 0; c < NCH; ++c) {
        if (c + 1 < NCH) {
            load_chunk(c + 1, (c + 1) & 1);
            asm volatile("cp.async.wait_group 1;" ::: "memory");
        } else {
            asm volatile("cp.async.wait_group 0;" ::: "memory");
        }
        __syncthreads();

        const uint32_t aT = sbase + (c & 1) * STAGE_BYTES;
        const uint32_t bT = aT + TILE_BYTES;

        #pragma unroll
        for (int ks = 0; ks < 4; ++ks) {
            uint32_t af[4][4];
            #pragma unroll
            for (int mf = 0; mf < 4; mf++) {
                const int c16 = ks * 2 + lhi;
                ldsm_x4(af[mf], aT + rowOffA[mf] +
                                ((c16 ^ (rA[mf] & 7)) << 4));
            }
            uint32_t bf[2][4];
            #pragma unroll
            for (int p = 0; p < 2; p++) {
                const int c16 = ks * 2 + (g8 & 1);
                ldsm_x4(bf[p], bT + rowOffB[p] +
                               ((c16 ^ (rB[p] & 7)) << 4));
            }
            #pragma unroll
            for (int mf = 0; mf < 4; mf++) {
                mma16816(acc[mf][0], af[mf], &bf[0][0]);
                mma16816(acc[mf][1], af[mf], &bf[0][2]);
                mma16816(acc[mf][2], af[mf], &bf[1][0]);
                mma16816(acc[mf][3], af[mf], &bf[1][2]);
            }
        }
        __syncthreads();
    }

    const int colBase = n0 + wn * 32 + 2 * (lane & 3);
    float2 b2[4];
    #pragma unroll
    for (int nf = 0; nf < 4; nf++)
        b2[nf] = *(const float2*)(bias + colBase + nf * 8);

    const int rowBase = m0 + wm * 64 + (lane >> 2);
    #pragma unroll
    for (int mf = 0; mf < 4; mf++) {
        const int r0 = rowBase + mf * 16;
        #pragma unroll
        for (int nf = 0; nf < 4; nf++) {
            const int col = colBase + nf * 8;
            float2 v0 = make_float2(acc[mf][nf][0] + b2[nf].x,
                                    acc[mf][nf][1] + b2[nf].y);
            float2 v1 = make_float2(acc[mf][nf][2] + b2[nf].x,
                                    acc[mf][nf][3] + b2[nf].y);
            *(float2*)(C + (size_t)r0 * Nn + col)       = v0;
            *(float2*)(C + (size_t)(r0 + 8) * Nn + col) = v1;
        }
    }
}

// ---------------------------------------------------------------------------
// Tensor-core attention (R14 structure): grid (NWIN, NHEAD), 128 threads.
// Internal q/k hi/lo split preserved; P hi-only; epilogue hi-only store.
// ---------------------------------------------------------------------------
#define A_QA1 0
#define A_QA2 8192
#define A_KB  16384
#define A_PH  24576
#define A_VT  32768
#define ASMEM (36864 + 128)

__device__ __forceinline__ uint32_t tile_addr(uint32_t tile, int row, int j) {
    return tile + row * 128 + ((((j >> 3) ^ (row & 7)) << 4) | ((j & 7) * 2));
}

__global__ __launch_bounds__(128)
void attn_tc_kernel()
{
    extern __shared__ uint8_t asm_raw[];
    const int tid  = threadIdx.x;
    const int warp = tid >> 5;
    const int lane = tid & 31;
    const int w    = blockIdx.x;
    const int h    = blockIdx.y;

    uint32_t sraw  = smem_u32(asm_raw);
    uint32_t sb    = (sraw + 127u) & ~127u;
    uint8_t* smem  = asm_raw + (sb - sraw);

    // ---- load qkv, build fp16 tiles (VT zero-padded inline, i to 64) ----
    const size_t base0 = (size_t)w * NTOK * QKV_COLS + h * HEADD;
    for (int idx = tid; idx < 64 * 8; idx += 128) {
        const int i = idx >> 3, c4 = idx & 7, d0 = c4 * 4;
        if (i < NTOK) {
            const float* gp = g_qkv + base0 + (size_t)i * QKV_COLS + d0;
            float4 qv = *(const float4*)gp;
            float4 kv = *(const float4*)(gp + 384);
            float4 vv = *(const float4*)(gp + 768);
            float qa[4] = {qv.x * SCALE_F, qv.y * SCALE_F,
                           qv.z * SCALE_F, qv.w * SCALE_F};
            float ka[4] = {kv.x, kv.y, kv.z, kv.w};
            float va[4] = {vv.x, vv.y, vv.z, vv.w};
            __half qh[4], ql[4], kh[4], kl[4];
            #pragma unroll
            for (int m = 0; m < 4; m++) {
                qh[m] = __float2half_rn(qa[m]);
                ql[m] = __float2half_rn(qa[m] - __half2float(qh[m]));
                kh[m] = __float2half_rn(ka[m]);
                kl[m] = __float2half_rn(ka[m] - __half2float(kh[m]));
            }
            uint32_t qhp[2] = {((uint32_t*)qh)[0], ((uint32_t*)qh)[1]};
            uint32_t qlp[2] = {((uint32_t*)ql)[0], ((uint32_t*)ql)[1]};
            uint32_t khp[2] = {((uint32_t*)kh)[0], ((uint32_t*)kh)[1]};
            uint32_t klp[2] = {((uint32_t*)kl)[0], ((uint32_t*)kl)[1]};
            *(uint2*)(smem + tile_addr(A_QA1, i, d0))      = make_uint2(qhp[0], qhp[1]);
            *(uint2*)(smem + tile_addr(A_QA1, i, d0 + 32)) = make_uint2(qhp[0], qhp[1]);
            *(uint2*)(smem + tile_addr(A_QA2, i, d0))      = make_uint2(qlp[0], qlp[1]);
            *(uint2*)(smem + tile_addr(A_QA2, i, d0 + 32)) = make_uint2(qlp[0], qlp[1]);
            *(uint2*)(smem + tile_addr(A_KB,  i, d0))      = make_uint2(khp[0], khp[1]);
            *(uint2*)(smem + tile_addr(A_KB,  i, d0 + 32)) = make_uint2(klp[0], klp[1]);
            #pragma unroll
            for (int m = 0; m < 4; m++)
                *(__half*)(smem + tile_addr(A_VT, d0 + m, i)) =
                    __float2half_rn(va[m]);
        } else {
            #pragma unroll
            for (int m = 0; m < 4; m++)
                *(__half*)(smem + tile_addr(A_VT, d0 + m, i)) = __half(0);
        }
    }
    __syncthreads();   // the only block-wide barrier

    const int l15 = lane & 15;
    const int lhi = lane >> 4;
    const int g8  = lane >> 3;
    const int l8  = lane & 7;

    // ---- QK^T: ks-outer, KB fragments loaded once per ks, both QA passes ----
    float sacc[8][4];
    #pragma unroll
    for (int nf = 0; nf < 8; nf++)
        #pragma unroll
        for (int e = 0; e < 4; e++) sacc[nf][e] = 0.0f;
    {
        const int rA = warp * 16 + l15;
        int rB[4];
        #pragma unroll
        for (int p = 0; p < 4; p++) rB[p] = p * 16 + (g8 >> 1) * 8 + l8;

        #pragma unroll
        for (int ks = 0; ks < 4; ks++) {
            const int c16a = ks * 2 + lhi;
            const uint32_t aoff = rA * 128 + ((c16a ^ (rA & 7)) << 4);
            uint32_t af1[4], af2[4];
            ldsm_x4(af1, sb + A_QA1 + aoff);
            ldsm_x4(af2, sb + A_QA2 + aoff);
            uint32_t bf[4][4];
            #pragma unroll
            for (int p = 0; p < 4; p++) {
                const int c16b = ks * 2 + (g8 & 1);
                ldsm_x4(bf[p], sb + A_KB + rB[p] * 128 +
                               ((c16b ^ (rB[p] & 7)) << 4));
            }
            #pragma unroll
            for (int p = 0; p < 4; p++) {
                mma16816(sacc[2 * p],     af1, &bf[p][0]);
                mma16816(sacc[2 * p + 1], af1, &bf[p][2]);
                mma16816(sacc[2 * p],     af2, &bf[p][0]);
                mma16816(sacc[2 * p + 1], af2, &bf[p][2]);
            }
        }
    }

    // ---- exp on registers + P store (hi only) + quad-shuffle row sums ----
    const int r0 = warp * 16 + (lane >> 2);
    const int r1 = r0 + 8;
    const int cb = 2 * (lane & 3);
    float rsum0 = 0.0f, rsum1 = 0.0f;
    {
        const float* bm = g_bm +
            (size_t)((w & (NW_IMG - 1)) * NHEAD + h) * BM_SLICE;
        #pragma unroll
        for (int nf = 0; nf < 8; nf++) {
            const int c = nf * 8 + cb;
            float2 bm0 = *(const float2*)(bm + r0 * BM_STRIDE + c);
            float2 bm1 = *(const float2*)(bm + r1 * BM_STRIDE + c);
            float e00 = 0.0f, e01 = 0.0f, e10 = 0.0f, e11 = 0.0f;
            if (c < NTOK) {
                e00 = fast_exp(sacc[nf][0] + bm0.x - EXP_SHIFT);
                e10 = fast_exp(sacc[nf][2] + bm1.x - EXP_SHIFT);
                if (c + 1 < NTOK) {
                    e01 = fast_exp(sacc[nf][1] + bm0.y - EXP_SHIFT);
                    e11 = fast_exp(sacc[nf][3] + bm1.y - EXP_SHIFT);
                }
            }
            rsum0 += e00 + e01;
            rsum1 += e10 + e11;
            *(__half2*)(smem + tile_addr(A_PH, r0, c)) =
                __halves2half2(__float2half_rn(e00), __float2half_rn(e01));
            *(__half2*)(smem + tile_addr(A_PH, r1, c)) =
                __halves2half2(__float2half_rn(e10), __float2half_rn(e11));
        }
    }
    rsum0 += __shfl_xor_sync(0xFFFFFFFF, rsum0, 1);
    rsum0 += __shfl_xor_sync(0xFFFFFFFF, rsum0, 2);
    rsum1 += __shfl_xor_sync(0xFFFFFFFF, rsum1, 1);
    rsum1 += __shfl_xor_sync(0xFFFFFFFF, rsum1, 2);
    const float rs0 = 1.0f / rsum0;
    const float rs1 = 1.0f / rsum1;
    __syncwarp();

    // ---- AV: PH @ VT -> O (single pass) ----
    float oacc[4][4];
    #pragma unroll
    for (int nf = 0; nf < 4; nf++)
        #pragma unroll
        for (int e = 0; e < 4; e++) oacc[nf][e] = 0.0f;
    {
        const int rA = warp * 16 + l15;
        int rB[2];
        #pragma unroll
        for (int p = 0; p < 2; p++) rB[p] = p * 16 + (g8 >> 1) * 8 + l8;

        #pragma unroll
        for (int ks = 0; ks < 4; ks++) {
            uint32_t af[4];
            const int c16a = ks * 2 + lhi;
            ldsm_x4(af, sb + A_PH + rA * 128 + ((c16a ^ (rA & 7)) << 4));
            uint32_t bf[2][4];
            #pragma unroll
            for (int p = 0; p < 2; p++) {
                const int c16b = ks * 2 + (g8 & 1);
                ldsm_x4(bf[p], sb + A_VT + rB[p] * 128 +
                               ((c16b ^ (rB[p] & 7)) << 4));
            }
            mma16816(oacc[0], af, &bf[0][0]);
            mma16816(oacc[1], af, &bf[0][2]);
            mma16816(oacc[2], af, &bf[1][0]);
            mma16816(oacc[3], af, &bf[1][2]);
        }
    }

    // ---- epilogue: scale by register rowsums, fp16 hi-only store ----
    {
        #pragma unroll
        for (int hf = 0; hf < 2; hf++) {
            const int row = hf ? r1 : r0;
            const float rs = hf ? rs1 : rs0;
            if (row < NTOK) {
                __half* gp = g_attn2 + (size_t)(w * NTOK + row) * KG + h * HEADD;
                #pragma unroll
                for (int nf = 0; nf < 4; nf++) {
                    const int d = nf * 8 + cb;
                    *(__half2*)(gp + d) = __halves2half2(
                        __float2half_rn(oacc[nf][hf * 2 + 0] * rs),
                        __float2half_rn(oacc[nf][hf * 2 + 1] * rs));
                }
            }
        }
    }
}

// ---------------------------------------------------------------------------
// Launch: prep_all(1), bm_prep(2), gemm1(3), attn(4), gemm3(5)
// ---------------------------------------------------------------------------
extern "C" void kernel_launch(void* const* d_in, const int* in_sizes, int n_in,
                              void* d_out, int out_size)
{
    const float* x         = (const float*)d_in[0];
    const float* mask      = (const float*)d_in[1];
    const float* rel_table = (const float*)d_in[2];
    const float* qkv_w     = (const float*)d_in[3];
    const float* qkv_b     = (const float*)d_in[4];
    const float* proj_w    = (const float*)d_in[5];
    const float* proj_b    = (const float*)d_in[6];
    const int*   rel_idx   = (const int*)d_in[7];
    float*       out       = (float*)d_out;

    void *qkv_p, *x2_p, *attn2_p, *wq2_p, *wp2_p;
    cudaGetSymbolAddress(&qkv_p,   g_qkv);
    cudaGetSymbolAddress(&x2_p,    g_x2);
    cudaGetSymbolAddress(&attn2_p, g_attn2);
    cudaGetSymbolAddress(&wq2_p,   g_wqkv2);
    cudaGetSymbolAddress(&wp2_p,   g_wproj2);

    cudaFuncSetAttribute(gemm_mma,
                         cudaFuncAttributeMaxDynamicSharedMemorySize, GSMEM);
    cudaFuncSetAttribute(attn_tc_kernel,
                         cudaFuncAttributeMaxDynamicSharedMemorySize, ASMEM);

    // 1) fp16 conversions
    {
        long t4x  = (long)MROWS * (DIM / 4);
        long t4wq = (long)QKV_COLS * (DIM / 4);
        long t4wp = (long)DIM * (DIM / 4);
        long tot  = t4x + t4wq + t4wp;
        prep_all<<<(unsigned)((tot + 255) / 256), 256>>>(
            x, qkv_w, proj_w,
            (__half*)x2_p, (__half*)wq2_p, (__half*)wp2_p,
            t4x, t4wq, t4wp);
    }
    // 2) bias+mask combine
    {
        long tot = (long)NW_IMG * NHEAD * NTOK * NTOK;
        bm_prep_kernel<<<(unsigned)((tot + 255) / 256), 256>>>(
            rel_table, rel_idx, mask);
    }
    // 3) QKV GEMM (K=384)
    {
        dim3 grid(QKV_COLS / 128, MROWS / 128);
        gemm_mma<<<grid, 256, GSMEM>>>(
            (const __half*)x2_p, (const __half*)wq2_p,
            qkv_b, (float*)qkv_p, QKV_COLS);
    }
    // 4) tensor-core attention
    {
        dim3 grid(NWIN, NHEAD);
        attn_tc_kernel<<<grid, 128, ASMEM>>>();
    }
    // 5) projection GEMM (K=384)
    {
        dim3 grid(DIM / 128, MROWS / 128);
        gemm_mma<<<grid, 256, GSMEM>>>(
            (const __half*)attn2_p, (const __half*)wp2_p,
            proj_b, out, DIM);
    }
}